// round 1
// baseline (speedup 1.0000x reference)
#include <cuda_runtime.h>
#include <cstdint>

#define V_  32000
#define E_  512
#define H_  1024
#define B_  16
#define T_  256
#define BT  4096
#define FH  4096

// ---------------- scratch (device globals; no allocation allowed) -----------
__device__ float g_zx[(size_t)BT * FH];      // [T][B][4H] = 64MB
__device__ float g_hseq[(size_t)BT * H_];    // [b*T+t][H] = 16MB
__device__ float g_h[B_ * H_];               // current h
__device__ unsigned g_bar_count;
__device__ unsigned g_bar_gen;

// ---------------- helpers ----------------------------------------------------
__device__ __forceinline__ uint32_t f2tf(float f) {
    uint32_t u;
    asm("cvt.rna.tf32.f32 %0, %1;" : "=r"(u) : "f"(f));
    return u;
}

__device__ __forceinline__ void mma_tf32(float* c,
                                         uint32_t a0, uint32_t a1, uint32_t a2, uint32_t a3,
                                         uint32_t b0, uint32_t b1) {
    asm volatile(
        "mma.sync.aligned.m16n8k8.row.col.f32.tf32.tf32.f32 "
        "{%0,%1,%2,%3}, {%4,%5,%6,%7}, {%8,%9}, {%0,%1,%2,%3};"
        : "+f"(c[0]), "+f"(c[1]), "+f"(c[2]), "+f"(c[3])
        : "r"(a0), "r"(a1), "r"(a2), "r"(a3), "r"(b0), "r"(b1));
}

__device__ __forceinline__ float sigf(float x) { return 1.0f / (1.0f + expf(-x)); }

// =============================================================================
// Generic tf32 GEMM:  C[M,N] = gather(A)[M,K] @ B[K,N] + bias[N]
// CTA tile 128x128, k-tile 32, 256 threads (8 warps as 2m x 4n of 64x32).
// blockIdx.x = m-tile (fast-varying -> all m-tiles share one B n-slice in L2)
// =============================================================================
#define GTM 128
#define GTN 128
#define GTK 32
#define AS_STRIDE 36
#define BS_STRIDE 132
#define AS_WORDS (GTM * AS_STRIDE)             // 4608
#define BS_WORDS (GTK * BS_STRIDE)             // 4224
#define GEMM_SMEM ((2 * AS_WORDS + 2 * BS_WORDS) * 4)  // 70656 B

template <bool GATHER>
__global__ void __launch_bounds__(256)
gemm_tf32(const float* __restrict__ A, const float* __restrict__ Bm,
          const float* __restrict__ bias, float* __restrict__ C,
          const int* __restrict__ xs, int M, int N, int K) {
    extern __shared__ uint32_t sm[];
    uint32_t* As = sm;                 // [2][AS_WORDS]
    uint32_t* Bs = sm + 2 * AS_WORDS;  // [2][BS_WORDS]

    const int tid  = threadIdx.x;
    const int lane = tid & 31;
    const int wid  = tid >> 5;
    const int m0   = blockIdx.x * GTM;
    const int n0   = blockIdx.y * GTN;
    const int wm   = (wid & 1) * 64;
    const int wn   = (wid >> 1) * 32;
    const int g    = lane >> 2;
    const int tg   = lane & 3;

    float acc[4][4][4];
#pragma unroll
    for (int i = 0; i < 4; i++)
#pragma unroll
        for (int j = 0; j < 4; j++)
#pragma unroll
            for (int k = 0; k < 4; k++) acc[i][j][k] = 0.0f;

    // resolve A source rows once
    int arow[4];
#pragma unroll
    for (int i = 0; i < 4; i++) {
        int idx = tid + i * 256;
        int r = m0 + (idx >> 3);
        if (GATHER) {
            // output row r = t*B + b ; embedding row = x[b*T + t]
            arow[i] = xs[(r & (B_ - 1)) * T_ + (r >> 4)];
        } else {
            arow[i] = r;
        }
    }

    const int KT = K / GTK;
    float4 av[4], bv[4];

    // ---- prologue: load tile 0 ----
#pragma unroll
    for (int i = 0; i < 4; i++) {
        int idx = tid + i * 256;
        int kq = idx & 7;
        av[i] = *reinterpret_cast<const float4*>(A + (size_t)arow[i] * K + kq * 4);
    }
#pragma unroll
    for (int i = 0; i < 4; i++) {
        int idx = tid + i * 256;
        int kr = idx >> 5, nq = idx & 31;
        bv[i] = *reinterpret_cast<const float4*>(Bm + (size_t)kr * N + n0 + nq * 4);
    }
    {
#pragma unroll
        for (int i = 0; i < 4; i++) {
            int idx = tid + i * 256;
            int row = idx >> 3, kq = idx & 7;
            uint4 u = {f2tf(av[i].x), f2tf(av[i].y), f2tf(av[i].z), f2tf(av[i].w)};
            *reinterpret_cast<uint4*>(As + row * AS_STRIDE + kq * 4) = u;
        }
#pragma unroll
        for (int i = 0; i < 4; i++) {
            int idx = tid + i * 256;
            int kr = idx >> 5, nq = idx & 31;
            uint4 u = {f2tf(bv[i].x), f2tf(bv[i].y), f2tf(bv[i].z), f2tf(bv[i].w)};
            *reinterpret_cast<uint4*>(Bs + kr * BS_STRIDE + nq * 4) = u;
        }
    }
    __syncthreads();

    for (int kt = 0; kt < KT; ++kt) {
        if (kt + 1 < KT) {
            int kofs = (kt + 1) * GTK;
#pragma unroll
            for (int i = 0; i < 4; i++) {
                int idx = tid + i * 256;
                int kq = idx & 7;
                av[i] = *reinterpret_cast<const float4*>(A + (size_t)arow[i] * K + kofs + kq * 4);
            }
#pragma unroll
            for (int i = 0; i < 4; i++) {
                int idx = tid + i * 256;
                int kr = idx >> 5, nq = idx & 31;
                bv[i] = *reinterpret_cast<const float4*>(Bm + (size_t)(kofs + kr) * N + n0 + nq * 4);
            }
        }
        const uint32_t* as = As + (kt & 1) * AS_WORDS;
        const uint32_t* bs = Bs + (kt & 1) * BS_WORDS;
#pragma unroll
        for (int kk = 0; kk < 4; kk++) {
            const int k8 = kk * 8;
            uint32_t bf[4][2];
#pragma unroll
            for (int nt = 0; nt < 4; nt++) {
                int ncol = wn + nt * 8 + g;
                bf[nt][0] = bs[(k8 + tg) * BS_STRIDE + ncol];
                bf[nt][1] = bs[(k8 + 4 + tg) * BS_STRIDE + ncol];
            }
#pragma unroll
            for (int mt = 0; mt < 4; mt++) {
                int r0 = wm + mt * 16 + g;
                uint32_t a0 = as[r0 * AS_STRIDE + k8 + tg];
                uint32_t a1 = as[(r0 + 8) * AS_STRIDE + k8 + tg];
                uint32_t a2 = as[r0 * AS_STRIDE + k8 + 4 + tg];
                uint32_t a3 = as[(r0 + 8) * AS_STRIDE + k8 + 4 + tg];
#pragma unroll
                for (int nt = 0; nt < 4; nt++)
                    mma_tf32(acc[mt][nt], a0, a1, a2, a3, bf[nt][0], bf[nt][1]);
            }
        }
        __syncthreads();
        if (kt + 1 < KT) {
            uint32_t* asd = As + ((kt + 1) & 1) * AS_WORDS;
            uint32_t* bsd = Bs + ((kt + 1) & 1) * BS_WORDS;
#pragma unroll
            for (int i = 0; i < 4; i++) {
                int idx = tid + i * 256;
                int row = idx >> 3, kq = idx & 7;
                uint4 u = {f2tf(av[i].x), f2tf(av[i].y), f2tf(av[i].z), f2tf(av[i].w)};
                *reinterpret_cast<uint4*>(asd + row * AS_STRIDE + kq * 4) = u;
            }
#pragma unroll
            for (int i = 0; i < 4; i++) {
                int idx = tid + i * 256;
                int kr = idx >> 5, nq = idx & 31;
                uint4 u = {f2tf(bv[i].x), f2tf(bv[i].y), f2tf(bv[i].z), f2tf(bv[i].w)};
                *reinterpret_cast<uint4*>(bsd + kr * BS_STRIDE + nq * 4) = u;
            }
            __syncthreads();
        }
    }

    // ---- epilogue ----
#pragma unroll
    for (int mt = 0; mt < 4; mt++) {
#pragma unroll
        for (int nt = 0; nt < 4; nt++) {
            int r = m0 + wm + mt * 16 + g;
            int c = n0 + wn + nt * 8 + 2 * tg;
            float2 bb = *reinterpret_cast<const float2*>(bias + c);
            float2 v0 = {acc[mt][nt][0] + bb.x, acc[mt][nt][1] + bb.y};
            float2 v1 = {acc[mt][nt][2] + bb.x, acc[mt][nt][3] + bb.y};
            *reinterpret_cast<float2*>(C + (size_t)r * N + c) = v0;
            *reinterpret_cast<float2*>(C + (size_t)(r + 8) * N + c) = v1;
        }
    }
}

// =============================================================================
// Persistent LSTM recurrence. 128 CTAs (1/SM, all resident), 256 threads.
// CTA b owns gate-columns j0..j0+7 -> z columns {q*H + j0 + jj, q=0..3}.
// Wr slice (1024x32, tf32) lives in shared for the whole kernel.
// c lives in registers of the gate threads. Grid barrier per timestep.
// =============================================================================
#define NCTA2 128
#define WR_STRIDE 36
#define HS_STRIDE 1028
#define WR_WORDS (H_ * WR_STRIDE)   // 36864
#define HS_WORDS (B_ * HS_STRIDE)   // 16448
#define ZS_FLOATS (2 * 16 * 32)     // 1024
#define RECUR_SMEM ((WR_WORDS + HS_WORDS + ZS_FLOATS) * 4)  // 217344 B

__global__ void __launch_bounds__(256, 1)
lstm_recur(const float* __restrict__ rec) {
    extern __shared__ uint32_t sm2[];
    uint32_t* Wr = sm2;
    uint32_t* Hs = sm2 + WR_WORDS;
    float* Zs = reinterpret_cast<float*>(sm2 + WR_WORDS + HS_WORDS);

    const int tid  = threadIdx.x;
    const int lane = tid & 31;
    const int wid  = tid >> 5;
    const int j0   = blockIdx.x * 8;
    const int g    = lane >> 2;
    const int tg   = lane & 3;

    // load Wr slice once: Wr[k][n], n -> global col (n/8)*H + j0 + (n&7)
    for (int i = tid; i < H_ * 32; i += 256) {
        int k = i >> 5, n = i & 31;
        int gcol = (n >> 3) * H_ + j0 + (n & 7);
        Wr[k * WR_STRIDE + n] = f2tf(rec[(size_t)k * FH + gcol]);
    }

    const int kh  = wid >> 2;  // k-half 0/1
    const int nt  = wid & 3;   // n-tile 0..3
    const int nn0 = nt * 8;

    const int gb = tid >> 3;  // gate thread -> batch (tid<128)
    const int gj = tid & 7;   // gate thread -> local j
    float creg = 0.0f;

    __syncthreads();

    for (int s = 0; s < T_; ++s) {
        // ---- stage h into shared (tf32) ----
        if (s == 0) {
            for (int i = tid; i < HS_WORDS; i += 256) Hs[i] = 0u;
        } else {
#pragma unroll
            for (int i = 0; i < 16; ++i) {
                int idx = tid + i * 256;          // 0..4095 float4s
                int b = idx >> 8, kq = idx & 255;
                float4 v = *reinterpret_cast<const float4*>(g_h + b * H_ + kq * 4);
                uint4 u = {f2tf(v.x), f2tf(v.y), f2tf(v.z), f2tf(v.w)};
                *reinterpret_cast<uint4*>(Hs + b * HS_STRIDE + kq * 4) = u;
            }
        }
        __syncthreads();

        // ---- z partial = h @ Wr_slice over this warp's k-half ----
        float ac[4][4];
#pragma unroll
        for (int i = 0; i < 4; i++)
#pragma unroll
            for (int j = 0; j < 4; j++) ac[i][j] = 0.0f;

        const int kbase = kh * 512;
#pragma unroll 4
        for (int kt = 0; kt < 64; ++kt) {
            int k0 = kbase + kt * 8;
            uint32_t a0 = Hs[g * HS_STRIDE + k0 + tg];
            uint32_t a1 = Hs[(g + 8) * HS_STRIDE + k0 + tg];
            uint32_t a2 = Hs[g * HS_STRIDE + k0 + 4 + tg];
            uint32_t a3 = Hs[(g + 8) * HS_STRIDE + k0 + 4 + tg];
            uint32_t b0 = Wr[(k0 + tg) * WR_STRIDE + nn0 + g];
            uint32_t b1 = Wr[(k0 + 4 + tg) * WR_STRIDE + nn0 + g];
            mma_tf32(ac[kt & 3], a0, a1, a2, a3, b0, b1);
        }
        float c0 = (ac[0][0] + ac[1][0]) + (ac[2][0] + ac[3][0]);
        float c1 = (ac[0][1] + ac[1][1]) + (ac[2][1] + ac[3][1]);
        float c2 = (ac[0][2] + ac[1][2]) + (ac[2][2] + ac[3][2]);
        float c3 = (ac[0][3] + ac[1][3]) + (ac[2][3] + ac[3][3]);

        float* zp = Zs + kh * 512;
        zp[g * 32 + nn0 + 2 * tg]           = c0;
        zp[g * 32 + nn0 + 2 * tg + 1]       = c1;
        zp[(g + 8) * 32 + nn0 + 2 * tg]     = c2;
        zp[(g + 8) * 32 + nn0 + 2 * tg + 1] = c3;
        __syncthreads();

        // ---- gates + state update (128 threads: (b, jj)) ----
        if (tid < 128) {
            const float* zx = g_zx + ((size_t)s * B_ + gb) * FH + j0 + gj;
            float zi = Zs[gb * 32 + gj]      + Zs[512 + gb * 32 + gj]      + zx[0];
            float zf = Zs[gb * 32 + 8 + gj]  + Zs[512 + gb * 32 + 8 + gj]  + zx[H_];
            float zg = Zs[gb * 32 + 16 + gj] + Zs[512 + gb * 32 + 16 + gj] + zx[2 * H_];
            float zo = Zs[gb * 32 + 24 + gj] + Zs[512 + gb * 32 + 24 + gj] + zx[3 * H_];
            creg = sigf(zf) * creg + sigf(zi) * tanhf(zg);
            float hh = sigf(zo) * tanhf(creg);
            g_h[gb * H_ + j0 + gj] = hh;
            g_hseq[((size_t)gb * T_ + s) * H_ + j0 + gj] = hh;
        }

        // ---- grid barrier (sense-reversing, generation counter) ----
        __syncthreads();
        if (tid == 0) {
            __threadfence();
            volatile unsigned* genp = &g_bar_gen;
            unsigned gen = *genp;
            unsigned arrived = atomicAdd(&g_bar_count, 1u);
            if (arrived == NCTA2 - 1) {
                atomicExch(&g_bar_count, 0u);
                __threadfence();
                *genp = gen + 1;
            } else {
                while (*genp == gen) { }
            }
            __threadfence();
        }
        __syncthreads();
    }
}

// =============================================================================
// host
// =============================================================================
extern "C" void kernel_launch(void* const* d_in, const int* in_sizes, int n_in,
                              void* d_out, int out_size) {
    (void)in_sizes; (void)n_in; (void)out_size;
    const int*   x    = (const int*)d_in[0];
    const float* emb  = (const float*)d_in[1];
    const float* W    = (const float*)d_in[2];
    const float* Wr   = (const float*)d_in[3];
    const float* bias = (const float*)d_in[4];
    const float* Wout = (const float*)d_in[5];
    const float* bout = (const float*)d_in[6];
    float* out = (float*)d_out;

    cudaFuncSetAttribute(gemm_tf32<true>,  cudaFuncAttributeMaxDynamicSharedMemorySize, GEMM_SMEM);
    cudaFuncSetAttribute(gemm_tf32<false>, cudaFuncAttributeMaxDynamicSharedMemorySize, GEMM_SMEM);
    cudaFuncSetAttribute(lstm_recur,       cudaFuncAttributeMaxDynamicSharedMemorySize, RECUR_SMEM);

    float* zx_p = nullptr;
    float* hseq_p = nullptr;
    cudaGetSymbolAddress((void**)&zx_p, g_zx);
    cudaGetSymbolAddress((void**)&hseq_p, g_hseq);

    // K1: zx[T*B, 4H] = emb[x] @ kernel + bias   (M=4096, N=4096, K=512)
    gemm_tf32<true><<<dim3(BT / GTM, FH / GTN), 256, GEMM_SMEM>>>(
        emb, W, bias, zx_p, x, BT, FH, E_);

    // K2: sequential LSTM over T=256 steps (persistent, grid-synced)
    lstm_recur<<<NCTA2, 256, RECUR_SMEM>>>(Wr);

    // K3: logits[BT, V] = hseq @ w_out + b_out   (M=4096, N=32000, K=1024)
    gemm_tf32<false><<<dim3(BT / GTM, V_ / GTN), 256, GEMM_SMEM>>>(
        hseq_p, Wout, bout, out, nullptr, BT, V_, H_);
}

// round 2
// speedup vs baseline: 1.1689x; 1.1689x over previous
#include <cuda_runtime.h>
#include <cstdint>

#define V_  32000
#define E_  512
#define H_  1024
#define B_  16
#define T_  256
#define BT  4096
#define FH  4096

// ---------------- scratch (device globals; no allocation allowed) -----------
__device__ float    g_zx[(size_t)BT * FH];       // [T][B][4H] 64MB
__device__ uint32_t g_hseq[(size_t)BT * H_];     // tf32 words 16MB
__device__ uint32_t g_h[B_ * H_];                // current h (tf32 words)
__device__ uint32_t g_emb_tf[(size_t)V_ * E_];   // 65MB
__device__ uint32_t g_w_tf[(size_t)E_ * FH];     // 8MB
__device__ uint32_t g_wout_tf[(size_t)H_ * V_];  // 131MB
__device__ unsigned g_bar_count;

// ---------------- helpers ----------------------------------------------------
__device__ __forceinline__ uint32_t f2tf(float f) {
    uint32_t u;
    asm("cvt.rna.tf32.f32 %0, %1;" : "=r"(u) : "f"(f));
    return u;
}

__device__ __forceinline__ void mma_tf32(float* c,
                                         uint32_t a0, uint32_t a1, uint32_t a2, uint32_t a3,
                                         uint32_t b0, uint32_t b1) {
    asm volatile(
        "mma.sync.aligned.m16n8k8.row.col.f32.tf32.tf32.f32 "
        "{%0,%1,%2,%3}, {%4,%5,%6,%7}, {%8,%9}, {%0,%1,%2,%3};"
        : "+f"(c[0]), "+f"(c[1]), "+f"(c[2]), "+f"(c[3])
        : "r"(a0), "r"(a1), "r"(a2), "r"(a3), "r"(b0), "r"(b1));
}

__device__ __forceinline__ float sigf(float x) { return 1.0f / (1.0f + expf(-x)); }

__device__ __forceinline__ void cp16(uint32_t dst, const void* src) {
    asm volatile("cp.async.cg.shared.global [%0], [%1], 16;\n" ::
                 "r"(dst), "l"(src) : "memory");
}
__device__ __forceinline__ void cp_commit() {
    asm volatile("cp.async.commit_group;" ::: "memory");
}
template <int N>
__device__ __forceinline__ void cp_wait() {
    asm volatile("cp.async.wait_group %0;" :: "n"(N) : "memory");
}

// ---------------- fp32 -> tf32 elementwise ------------------------------------
__global__ void cvt_tf32(const float4* __restrict__ src, uint4* __restrict__ dst, int n4) {
    int i = blockIdx.x * blockDim.x + threadIdx.x;
    int stride = gridDim.x * blockDim.x;
    for (; i < n4; i += stride) {
        float4 v = src[i];
        dst[i] = make_uint4(f2tf(v.x), f2tf(v.y), f2tf(v.z), f2tf(v.w));
    }
}

// =============================================================================
// Pipelined tf32 GEMM: C[M,N] = gather(A)[M,K] @ B[K,N] + bias[N]
// A,B already tf32 words. CTA tile 128x128, k=32, 4-stage cp.async.
// 256 threads = 8 warps (2m x 4n of 64x32). blockIdx.x = m-tile (fast).
// =============================================================================
#define GTM 128
#define GTN 128
#define GTK 32
#define PS  4
#define AS_STRIDE 36
#define BS_STRIDE 132
#define AS_WORDS (GTM * AS_STRIDE)   // 4608
#define BS_WORDS (GTK * BS_STRIDE)   // 4224
#define GEMM_SMEM (PS * (AS_WORDS + BS_WORDS) * 4)  // 141312 B

template <bool GATHER>
__global__ void __launch_bounds__(256)
gemm_pipe(const uint32_t* __restrict__ A, const uint32_t* __restrict__ Bm,
          const float* __restrict__ bias, float* __restrict__ C,
          const int* __restrict__ xs, int M, int N, int K) {
    extern __shared__ uint32_t sm[];
    uint32_t* As = sm;
    uint32_t* Bs = sm + PS * AS_WORDS;

    uint32_t sbase;
    asm("{.reg .u64 t; cvta.to.shared.u64 t, %1; cvt.u32.u64 %0, t;}"
        : "=r"(sbase) : "l"(sm));
    const uint32_t a_base = sbase;
    const uint32_t b_base = sbase + PS * AS_WORDS * 4;

    const int tid  = threadIdx.x;
    const int lane = tid & 31;
    const int wid  = tid >> 5;
    const int m0   = blockIdx.x * GTM;
    const int n0   = blockIdx.y * GTN;
    const int wm   = (wid & 1) * 64;
    const int wn   = (wid >> 1) * 32;
    const int g    = lane >> 2;
    const int tg   = lane & 3;

    float acc[4][4][4];
#pragma unroll
    for (int i = 0; i < 4; i++)
#pragma unroll
        for (int j = 0; j < 4; j++)
#pragma unroll
            for (int k = 0; k < 4; k++) acc[i][j][k] = 0.0f;

    // resolve A source rows once
    int arow[4];
#pragma unroll
    for (int i = 0; i < 4; i++) {
        int idx = tid + i * 256;
        int r = m0 + (idx >> 3);
        arow[i] = GATHER ? xs[(r & (B_ - 1)) * T_ + (r >> 4)] : r;
    }

    const int KT = K / GTK;

    auto load_stage = [&](int st, int kt) {
        const int k0 = kt * GTK;
#pragma unroll
        for (int i = 0; i < 4; i++) {
            int idx = tid + i * 256;
            int row = idx >> 3, kq = idx & 7;
            const void* src = A + (size_t)arow[i] * K + k0 + kq * 4;
            cp16(a_base + (st * AS_WORDS + row * AS_STRIDE + kq * 4) * 4, src);
        }
#pragma unroll
        for (int i = 0; i < 4; i++) {
            int idx = tid + i * 256;
            int kr = idx >> 5, nq = idx & 31;
            const void* src = Bm + (size_t)(k0 + kr) * N + n0 + nq * 4;
            cp16(b_base + (st * BS_WORDS + kr * BS_STRIDE + nq * 4) * 4, src);
        }
    };

    // prologue: stages 0..PS-2
#pragma unroll
    for (int p = 0; p < PS - 1; ++p) {
        load_stage(p, p);
        cp_commit();
    }

    for (int kt = 0; kt < KT; ++kt) {
        cp_wait<PS - 2>();
        __syncthreads();
        if (kt + PS - 1 < KT) load_stage((kt + PS - 1) % PS, kt + PS - 1);
        cp_commit();  // always commit to keep group accounting simple

        const uint32_t* as = As + (kt % PS) * AS_WORDS;
        const uint32_t* bs = Bs + (kt % PS) * BS_WORDS;
#pragma unroll
        for (int kk = 0; kk < 4; kk++) {
            const int k8 = kk * 8;
            uint32_t bf[4][2];
#pragma unroll
            for (int nt = 0; nt < 4; nt++) {
                int ncol = wn + nt * 8 + g;
                bf[nt][0] = bs[(k8 + tg) * BS_STRIDE + ncol];
                bf[nt][1] = bs[(k8 + 4 + tg) * BS_STRIDE + ncol];
            }
#pragma unroll
            for (int mt = 0; mt < 4; mt++) {
                int r0 = wm + mt * 16 + g;
                uint32_t a0 = as[r0 * AS_STRIDE + k8 + tg];
                uint32_t a1 = as[(r0 + 8) * AS_STRIDE + k8 + tg];
                uint32_t a2 = as[r0 * AS_STRIDE + k8 + 4 + tg];
                uint32_t a3 = as[(r0 + 8) * AS_STRIDE + k8 + 4 + tg];
#pragma unroll
                for (int nt = 0; nt < 4; nt++)
                    mma_tf32(acc[mt][nt], a0, a1, a2, a3, bf[nt][0], bf[nt][1]);
            }
        }
    }

    // ---- epilogue ----
#pragma unroll
    for (int mt = 0; mt < 4; mt++) {
#pragma unroll
        for (int nt = 0; nt < 4; nt++) {
            int r = m0 + wm + mt * 16 + g;
            int c = n0 + wn + nt * 8 + 2 * tg;
            float2 bb = *reinterpret_cast<const float2*>(bias + c);
            float2 v0 = {acc[mt][nt][0] + bb.x, acc[mt][nt][1] + bb.y};
            float2 v1 = {acc[mt][nt][2] + bb.x, acc[mt][nt][3] + bb.y};
            *reinterpret_cast<float2*>(C + (size_t)r * N + c) = v0;
            *reinterpret_cast<float2*>(C + (size_t)(r + 8) * N + c) = v1;
        }
    }
}

// =============================================================================
// Persistent LSTM recurrence. 128 CTAs, 256 threads.
// Wr slice (1024x32 tf32) resident in shared. c in registers.
// Monotone-counter grid barrier; zx prefetched ahead of the mma loop.
// =============================================================================
#define NCTA2 128
#define WR_STRIDE 36
#define HS_STRIDE 1028
#define WR_WORDS (H_ * WR_STRIDE)   // 36864
#define HS_WORDS (B_ * HS_STRIDE)   // 16448
#define ZS_FLOATS (2 * 16 * 32)     // 1024
#define RECUR_SMEM ((WR_WORDS + HS_WORDS + ZS_FLOATS) * 4)  // 217344 B

__global__ void __launch_bounds__(256, 1)
lstm_recur(const float* __restrict__ rec) {
    extern __shared__ uint32_t sm2[];
    uint32_t* Wr = sm2;
    uint32_t* Hs = sm2 + WR_WORDS;
    float* Zs = reinterpret_cast<float*>(sm2 + WR_WORDS + HS_WORDS);

    const int tid  = threadIdx.x;
    const int lane = tid & 31;
    const int wid  = tid >> 5;
    const int j0   = blockIdx.x * 8;
    const int g    = lane >> 2;
    const int tg   = lane & 3;

    // load Wr slice once: Wr[k][n], n -> global col (n/8)*H + j0 + (n&7)
    for (int i = tid; i < H_ * 32; i += 256) {
        int k = i >> 5, n = i & 31;
        int gcol = (n >> 3) * H_ + j0 + (n & 7);
        Wr[k * WR_STRIDE + n] = f2tf(rec[(size_t)k * FH + gcol]);
    }

    const int kh  = wid >> 2;
    const int nt  = wid & 3;
    const int nn0 = nt * 8;

    const int gb = tid >> 3;
    const int gj = tid & 7;
    float creg = 0.0f;

    __syncthreads();

    for (int s = 0; s < T_; ++s) {
        // ---- prefetch zx (independent of h; hidden behind staging + mma) ----
        float zxi = 0.f, zxf = 0.f, zxg = 0.f, zxo = 0.f;
        if (tid < 128) {
            const float* zx = g_zx + ((size_t)s * B_ + gb) * FH + j0 + gj;
            zxi = zx[0];
            zxf = zx[H_];
            zxg = zx[2 * H_];
            zxo = zx[3 * H_];
        }

        // ---- stage h into shared (already tf32 words) ----
        if (s == 0) {
            for (int i = tid; i < HS_WORDS; i += 256) Hs[i] = 0u;
        } else {
#pragma unroll
            for (int i = 0; i < 16; ++i) {
                int idx = tid + i * 256;   // 0..4095 uint4s
                int b = idx >> 8, kq = idx & 255;
                uint4 v = *reinterpret_cast<const uint4*>(g_h + b * H_ + kq * 4);
                *reinterpret_cast<uint4*>(Hs + b * HS_STRIDE + kq * 4) = v;
            }
        }
        __syncthreads();

        // ---- z partial = h @ Wr_slice over this warp's k-half ----
        float ac[4][4];
#pragma unroll
        for (int i = 0; i < 4; i++)
#pragma unroll
            for (int j = 0; j < 4; j++) ac[i][j] = 0.0f;

        const int kbase = kh * 512;
#pragma unroll 4
        for (int kt = 0; kt < 64; ++kt) {
            int k0 = kbase + kt * 8;
            uint32_t a0 = Hs[g * HS_STRIDE + k0 + tg];
            uint32_t a1 = Hs[(g + 8) * HS_STRIDE + k0 + tg];
            uint32_t a2 = Hs[g * HS_STRIDE + k0 + 4 + tg];
            uint32_t a3 = Hs[(g + 8) * HS_STRIDE + k0 + 4 + tg];
            uint32_t b0 = Wr[(k0 + tg) * WR_STRIDE + nn0 + g];
            uint32_t b1 = Wr[(k0 + 4 + tg) * WR_STRIDE + nn0 + g];
            mma_tf32(ac[kt & 3], a0, a1, a2, a3, b0, b1);
        }
        float c0 = (ac[0][0] + ac[1][0]) + (ac[2][0] + ac[3][0]);
        float c1 = (ac[0][1] + ac[1][1]) + (ac[2][1] + ac[3][1]);
        float c2 = (ac[0][2] + ac[1][2]) + (ac[2][2] + ac[3][2]);
        float c3 = (ac[0][3] + ac[1][3]) + (ac[2][3] + ac[3][3]);

        float* zp = Zs + kh * 512;
        zp[g * 32 + nn0 + 2 * tg]           = c0;
        zp[g * 32 + nn0 + 2 * tg + 1]       = c1;
        zp[(g + 8) * 32 + nn0 + 2 * tg]     = c2;
        zp[(g + 8) * 32 + nn0 + 2 * tg + 1] = c3;
        __syncthreads();

        // ---- gates + state update (128 threads: (b, jj)) ----
        if (tid < 128) {
            float zi = Zs[gb * 32 + gj]      + Zs[512 + gb * 32 + gj]      + zxi;
            float zf = Zs[gb * 32 + 8 + gj]  + Zs[512 + gb * 32 + 8 + gj]  + zxf;
            float zg = Zs[gb * 32 + 16 + gj] + Zs[512 + gb * 32 + 16 + gj] + zxg;
            float zo = Zs[gb * 32 + 24 + gj] + Zs[512 + gb * 32 + 24 + gj] + zxo;
            creg = sigf(zf) * creg + sigf(zi) * tanhf(zg);
            float hh = sigf(zo) * tanhf(creg);
            uint32_t hw = f2tf(hh);
            g_h[gb * H_ + j0 + gj] = hw;
            g_hseq[((size_t)gb * T_ + s) * H_ + j0 + gj] = hw;
            __threadfence();   // make h stores GPU-visible before arrival
        }
        __syncthreads();

        // ---- grid barrier: monotone counter, release-add / acquire-poll ----
        if (tid == 0) {
            unsigned target = (unsigned)NCTA2 * (unsigned)(s + 1);
            asm volatile("red.release.gpu.global.add.u32 [%0], %1;" ::
                         "l"(&g_bar_count), "r"(1u) : "memory");
            unsigned v;
            do {
                asm volatile("ld.acquire.gpu.global.u32 %0, [%1];"
                             : "=r"(v) : "l"(&g_bar_count) : "memory");
            } while (v < target);
        }
        __syncthreads();
    }
}

// =============================================================================
// host
// =============================================================================
extern "C" void kernel_launch(void* const* d_in, const int* in_sizes, int n_in,
                              void* d_out, int out_size) {
    (void)in_sizes; (void)n_in; (void)out_size;
    const int*   x    = (const int*)d_in[0];
    const float* emb  = (const float*)d_in[1];
    const float* W    = (const float*)d_in[2];
    const float* Wr   = (const float*)d_in[3];
    const float* bias = (const float*)d_in[4];
    const float* Wout = (const float*)d_in[5];
    const float* bout = (const float*)d_in[6];
    float* out = (float*)d_out;

    cudaFuncSetAttribute(gemm_pipe<true>,  cudaFuncAttributeMaxDynamicSharedMemorySize, GEMM_SMEM);
    cudaFuncSetAttribute(gemm_pipe<false>, cudaFuncAttributeMaxDynamicSharedMemorySize, GEMM_SMEM);
    cudaFuncSetAttribute(lstm_recur,       cudaFuncAttributeMaxDynamicSharedMemorySize, RECUR_SMEM);

    float* zx_p = nullptr;
    uint32_t *hseq_p = nullptr, *emb_tf = nullptr, *w_tf = nullptr, *wout_tf = nullptr;
    unsigned* bar_p = nullptr;
    cudaGetSymbolAddress((void**)&zx_p, g_zx);
    cudaGetSymbolAddress((void**)&hseq_p, g_hseq);
    cudaGetSymbolAddress((void**)&emb_tf, g_emb_tf);
    cudaGetSymbolAddress((void**)&w_tf, g_w_tf);
    cudaGetSymbolAddress((void**)&wout_tf, g_wout_tf);
    cudaGetSymbolAddress((void**)&bar_p, g_bar_count);

    // reset grid-barrier counter (graph-capturable)
    cudaMemsetAsync(bar_p, 0, sizeof(unsigned));

    // pre-convert weights to tf32 (round-to-nearest; exact for later mma loads)
    cvt_tf32<<<1184, 256>>>((const float4*)emb,  (uint4*)emb_tf,  (V_ * E_) / 4);
    cvt_tf32<<<1184, 256>>>((const float4*)W,    (uint4*)w_tf,    (E_ * FH) / 4);
    cvt_tf32<<<1184, 256>>>((const float4*)Wout, (uint4*)wout_tf, (H_ * V_) / 4);

    // K1: zx[T*B, 4H] = emb[x] @ kernel + bias   (M=4096, N=4096, K=512)
    gemm_pipe<true><<<dim3(BT / GTM, FH / GTN), 256, GEMM_SMEM>>>(
        emb_tf, w_tf, bias, zx_p, x, BT, FH, E_);

    // K2: sequential LSTM over T=256 steps (persistent, grid-synced)
    lstm_recur<<<NCTA2, 256, RECUR_SMEM>>>(Wr);

    // K3: logits[BT, V] = hseq @ w_out + b_out   (M=4096, N=32000, K=1024)
    gemm_pipe<false><<<dim3(BT / GTM, V_ / GTN), 256, GEMM_SMEM>>>(
        (const uint32_t*)hseq_p, wout_tf, bout, out, nullptr, BT, V_, H_);
}

// round 4
// speedup vs baseline: 1.3612x; 1.1645x over previous
#include <cuda_runtime.h>
#include <cstdint>

#define V_  32000
#define E_  512
#define H_  1024
#define B_  16
#define T_  256
#define BT  4096
#define FH  4096

// ---------------- scratch (device globals; no allocation allowed) -----------
__device__ float    g_zx[(size_t)BT * FH];       // [T][B][4H] 64MB
__device__ uint32_t g_hseq[(size_t)BT * H_];     // tf32 words 16MB
__device__ uint32_t g_h[B_ * H_];                // current h (tf32 words)
__device__ uint32_t g_emb_tf[(size_t)V_ * E_];   // 65MB
__device__ uint32_t g_w_tf[(size_t)E_ * FH];     // 8MB
__device__ uint32_t g_wout_tf[(size_t)H_ * V_];  // 131MB
__device__ unsigned g_bar_count;

// ---------------- helpers ----------------------------------------------------
__device__ __forceinline__ uint32_t f2tf(float f) {
    uint32_t u;
    asm("cvt.rna.tf32.f32 %0, %1;" : "=r"(u) : "f"(f));
    return u;
}

__device__ __forceinline__ void mma_tf32(float* c,
                                         uint32_t a0, uint32_t a1, uint32_t a2, uint32_t a3,
                                         uint32_t b0, uint32_t b1) {
    asm volatile(
        "mma.sync.aligned.m16n8k8.row.col.f32.tf32.tf32.f32 "
        "{%0,%1,%2,%3}, {%4,%5,%6,%7}, {%8,%9}, {%0,%1,%2,%3};"
        : "+f"(c[0]), "+f"(c[1]), "+f"(c[2]), "+f"(c[3])
        : "r"(a0), "r"(a1), "r"(a2), "r"(a3), "r"(b0), "r"(b1));
}

__device__ __forceinline__ float sigf(float x) { return 1.0f / (1.0f + expf(-x)); }

__device__ __forceinline__ void cp16(uint32_t dst, const void* src) {
    asm volatile("cp.async.cg.shared.global [%0], [%1], 16;\n" ::
                 "r"(dst), "l"(src) : "memory");
}
__device__ __forceinline__ void cp_commit() {
    asm volatile("cp.async.commit_group;" ::: "memory");
}
template <int N>
__device__ __forceinline__ void cp_wait() {
    asm volatile("cp.async.wait_group %0;" :: "n"(N) : "memory");
}

// ---------------- fp32 -> tf32 elementwise ------------------------------------
__global__ void cvt_tf32(const float4* __restrict__ src, uint4* __restrict__ dst, int n4) {
    int i = blockIdx.x * blockDim.x + threadIdx.x;
    int stride = gridDim.x * blockDim.x;
    for (; i < n4; i += stride) {
        float4 v = src[i];
        dst[i] = make_uint4(f2tf(v.x), f2tf(v.y), f2tf(v.z), f2tf(v.w));
    }
}

// =============================================================================
// Pipelined tf32 GEMM: C[M,N] = gather(A)[M,K] @ B[K,N] + bias[N]
// A,B already tf32 words. CTA tile 128x128, k=32, 3-stage cp.async.
// 256 threads = 8 warps (2m x 4n of 64x32). blockIdx.x = m-tile (fast).
// 2 CTAs / SM (smem 106KB, regs capped at 128 via launch_bounds).
// =============================================================================
#define GTM 128
#define GTN 128
#define GTK 32
#define PS  3
#define AS_STRIDE 36
#define BS_STRIDE 132
#define AS_WORDS (GTM * AS_STRIDE)   // 4608
#define BS_WORDS (GTK * BS_STRIDE)   // 4224
#define GEMM_SMEM (PS * (AS_WORDS + BS_WORDS) * 4)  // 105984 B

template <bool GATHER>
__global__ void __launch_bounds__(256, 2)
gemm_pipe(const uint32_t* __restrict__ A, const uint32_t* __restrict__ Bm,
          const float* __restrict__ bias, float* __restrict__ C,
          const int* __restrict__ xs, int M, int N, int K) {
    extern __shared__ uint32_t sm[];
    uint32_t* As = sm;
    uint32_t* Bs = sm + PS * AS_WORDS;

    uint32_t sbase;
    asm("{.reg .u64 t; cvta.to.shared.u64 t, %1; cvt.u32.u64 %0, t;}"
        : "=r"(sbase) : "l"(sm));
    const uint32_t a_base = sbase;
    const uint32_t b_base = sbase + PS * AS_WORDS * 4;

    const int tid  = threadIdx.x;
    const int lane = tid & 31;
    const int wid  = tid >> 5;
    const int m0   = blockIdx.x * GTM;
    const int n0   = blockIdx.y * GTN;
    const int wm   = (wid & 1) * 64;
    const int wn   = (wid >> 1) * 32;
    const int g    = lane >> 2;
    const int tg   = lane & 3;

    float acc[4][4][4];
#pragma unroll
    for (int i = 0; i < 4; i++)
#pragma unroll
        for (int j = 0; j < 4; j++)
#pragma unroll
            for (int k = 0; k < 4; k++) acc[i][j][k] = 0.0f;

    // resolve A source rows once
    int arow[4];
#pragma unroll
    for (int i = 0; i < 4; i++) {
        int idx = tid + i * 256;
        int r = m0 + (idx >> 3);
        arow[i] = GATHER ? xs[(r & (B_ - 1)) * T_ + (r >> 4)] : r;
    }

    const int KT = K / GTK;

    auto load_stage = [&](int st, int kt) {
        const int k0 = kt * GTK;
#pragma unroll
        for (int i = 0; i < 4; i++) {
            int idx = tid + i * 256;
            int row = idx >> 3, kq = idx & 7;
            const void* src = A + (size_t)arow[i] * K + k0 + kq * 4;
            cp16(a_base + (st * AS_WORDS + row * AS_STRIDE + kq * 4) * 4, src);
        }
#pragma unroll
        for (int i = 0; i < 4; i++) {
            int idx = tid + i * 256;
            int kr = idx >> 5, nq = idx & 31;
            const void* src = Bm + (size_t)(k0 + kr) * N + n0 + nq * 4;
            cp16(b_base + (st * BS_WORDS + kr * BS_STRIDE + nq * 4) * 4, src);
        }
    };

    // prologue: stages 0..PS-2
#pragma unroll
    for (int p = 0; p < PS - 1; ++p) {
        load_stage(p, p);
        cp_commit();
    }

    for (int kt = 0; kt < KT; ++kt) {
        cp_wait<PS - 2>();
        __syncthreads();
        if (kt + PS - 1 < KT) load_stage((kt + PS - 1) % PS, kt + PS - 1);
        cp_commit();  // always commit to keep group accounting simple

        const uint32_t* as = As + (kt % PS) * AS_WORDS;
        const uint32_t* bs = Bs + (kt % PS) * BS_WORDS;
#pragma unroll
        for (int kk = 0; kk < 4; kk++) {
            const int k8 = kk * 8;
            uint32_t bf[4][2];
#pragma unroll
            for (int nt = 0; nt < 4; nt++) {
                int ncol = wn + nt * 8 + g;
                bf[nt][0] = bs[(k8 + tg) * BS_STRIDE + ncol];
                bf[nt][1] = bs[(k8 + 4 + tg) * BS_STRIDE + ncol];
            }
#pragma unroll
            for (int mt = 0; mt < 4; mt++) {
                int r0 = wm + mt * 16 + g;
                uint32_t a0 = as[r0 * AS_STRIDE + k8 + tg];
                uint32_t a1 = as[(r0 + 8) * AS_STRIDE + k8 + tg];
                uint32_t a2 = as[r0 * AS_STRIDE + k8 + 4 + tg];
                uint32_t a3 = as[(r0 + 8) * AS_STRIDE + k8 + 4 + tg];
#pragma unroll
                for (int nt = 0; nt < 4; nt++)
                    mma_tf32(acc[mt][nt], a0, a1, a2, a3, bf[nt][0], bf[nt][1]);
            }
        }
    }

    // ---- epilogue ----
#pragma unroll
    for (int mt = 0; mt < 4; mt++) {
#pragma unroll
        for (int nt = 0; nt < 4; nt++) {
            int r = m0 + wm + mt * 16 + g;
            int c = n0 + wn + nt * 8 + 2 * tg;
            float2 bb = *reinterpret_cast<const float2*>(bias + c);
            float2 v0 = {acc[mt][nt][0] + bb.x, acc[mt][nt][1] + bb.y};
            float2 v1 = {acc[mt][nt][2] + bb.x, acc[mt][nt][3] + bb.y};
            *reinterpret_cast<float2*>(C + (size_t)r * N + c) = v0;
            *reinterpret_cast<float2*>(C + (size_t)(r + 8) * N + c) = v1;
        }
    }
}

// =============================================================================
// Persistent LSTM recurrence. 128 CTAs, 256 threads.
// Wr slice (1024x32 tf32) resident in shared. c in registers.
// Monotone-counter grid barrier (release-add / acquire-poll, no extra fence).
// =============================================================================
#define NCTA2 128
#define WR_STRIDE 36
#define HS_STRIDE 1028
#define WR_WORDS (H_ * WR_STRIDE)   // 36864
#define HS_WORDS (B_ * HS_STRIDE)   // 16448
#define ZS_FLOATS (2 * 16 * 32)     // 1024
#define RECUR_SMEM ((WR_WORDS + HS_WORDS + ZS_FLOATS) * 4)  // 217344 B

__global__ void __launch_bounds__(256, 1)
lstm_recur(const float* __restrict__ rec) {
    extern __shared__ uint32_t sm2[];
    uint32_t* Wr = sm2;
    uint32_t* Hs = sm2 + WR_WORDS;
    float* Zs = reinterpret_cast<float*>(sm2 + WR_WORDS + HS_WORDS);

    const int tid  = threadIdx.x;
    const int lane = tid & 31;
    const int wid  = tid >> 5;
    const int j0   = blockIdx.x * 8;
    const int g    = lane >> 2;
    const int tg   = lane & 3;

    // load Wr slice once: Wr[k][n], n -> global col (n/8)*H + j0 + (n&7)
    for (int i = tid; i < H_ * 32; i += 256) {
        int k = i >> 5, n = i & 31;
        int gcol = (n >> 3) * H_ + j0 + (n & 7);
        Wr[k * WR_STRIDE + n] = f2tf(rec[(size_t)k * FH + gcol]);
    }

    const int kh  = wid >> 2;
    const int nt  = wid & 3;
    const int nn0 = nt * 8;

    const int gb = tid >> 3;
    const int gj = tid & 7;
    float creg = 0.0f;

    __syncthreads();

    for (int s = 0; s < T_; ++s) {
        // ---- prefetch zx (independent of h) ----
        float zxi = 0.f, zxf = 0.f, zxg = 0.f, zxo = 0.f;
        if (tid < 128) {
            const float* zx = g_zx + ((size_t)s * B_ + gb) * FH + j0 + gj;
            zxi = zx[0];
            zxf = zx[H_];
            zxg = zx[2 * H_];
            zxo = zx[3 * H_];
        }

        // ---- stage h into shared (already tf32 words) ----
        if (s == 0) {
            for (int i = tid; i < HS_WORDS; i += 256) Hs[i] = 0u;
        } else {
#pragma unroll
            for (int i = 0; i < 16; ++i) {
                int idx = tid + i * 256;   // 0..4095 uint4s
                int b = idx >> 8, kq = idx & 255;
                uint4 v = *reinterpret_cast<const uint4*>(g_h + b * H_ + kq * 4);
                *reinterpret_cast<uint4*>(Hs + b * HS_STRIDE + kq * 4) = v;
            }
        }
        __syncthreads();

        // ---- z partial = h @ Wr_slice over this warp's k-half ----
        float ac[4][4];
#pragma unroll
        for (int i = 0; i < 4; i++)
#pragma unroll
            for (int j = 0; j < 4; j++) ac[i][j] = 0.0f;

        const int kbase = kh * 512;
#pragma unroll 4
        for (int kt = 0; kt < 64; ++kt) {
            int k0 = kbase + kt * 8;
            uint32_t a0 = Hs[g * HS_STRIDE + k0 + tg];
            uint32_t a1 = Hs[(g + 8) * HS_STRIDE + k0 + tg];
            uint32_t a2 = Hs[g * HS_STRIDE + k0 + 4 + tg];
            uint32_t a3 = Hs[(g + 8) * HS_STRIDE + k0 + 4 + tg];
            uint32_t b0 = Wr[(k0 + tg) * WR_STRIDE + nn0 + g];
            uint32_t b1 = Wr[(k0 + 4 + tg) * WR_STRIDE + nn0 + g];
            mma_tf32(ac[kt & 3], a0, a1, a2, a3, b0, b1);
        }
        float c0 = (ac[0][0] + ac[1][0]) + (ac[2][0] + ac[3][0]);
        float c1 = (ac[0][1] + ac[1][1]) + (ac[2][1] + ac[3][1]);
        float c2 = (ac[0][2] + ac[1][2]) + (ac[2][2] + ac[3][2]);
        float c3 = (ac[0][3] + ac[1][3]) + (ac[2][3] + ac[3][3]);

        float* zp = Zs + kh * 512;
        zp[g * 32 + nn0 + 2 * tg]           = c0;
        zp[g * 32 + nn0 + 2 * tg + 1]       = c1;
        zp[(g + 8) * 32 + nn0 + 2 * tg]     = c2;
        zp[(g + 8) * 32 + nn0 + 2 * tg + 1] = c3;
        __syncthreads();

        // ---- gates + state update (128 threads: (b, jj)) ----
        if (tid < 128) {
            float zi = Zs[gb * 32 + gj]      + Zs[512 + gb * 32 + gj]      + zxi;
            float zf = Zs[gb * 32 + 8 + gj]  + Zs[512 + gb * 32 + 8 + gj]  + zxf;
            float zg = Zs[gb * 32 + 16 + gj] + Zs[512 + gb * 32 + 16 + gj] + zxg;
            float zo = Zs[gb * 32 + 24 + gj] + Zs[512 + gb * 32 + 24 + gj] + zxo;
            creg = sigf(zf) * creg + sigf(zi) * tanhf(zg);
            float hh = sigf(zo) * tanhf(creg);
            uint32_t hw = f2tf(hh);
            g_h[gb * H_ + j0 + gj] = hw;
            g_hseq[((size_t)gb * T_ + s) * H_ + j0 + gj] = hw;
        }
        __syncthreads();

        // ---- grid barrier: monotone counter; release-add orders the h stores
        // (syncthreads gives intra-CTA happens-before into the releasing thread)
        if (tid == 0) {
            unsigned target = (unsigned)NCTA2 * (unsigned)(s + 1);
            asm volatile("red.release.gpu.global.add.u32 [%0], %1;" ::
                         "l"(&g_bar_count), "r"(1u) : "memory");
            unsigned v;
            do {
                asm volatile("ld.acquire.gpu.global.u32 %0, [%1];"
                             : "=r"(v) : "l"(&g_bar_count) : "memory");
            } while (v < target);
        }
        __syncthreads();
    }
}

// =============================================================================
// host
// =============================================================================
extern "C" void kernel_launch(void* const* d_in, const int* in_sizes, int n_in,
                              void* d_out, int out_size) {
    (void)in_sizes; (void)n_in; (void)out_size;
    const int*   x    = (const int*)d_in[0];
    const float* emb  = (const float*)d_in[1];
    const float* W    = (const float*)d_in[2];
    const float* Wr   = (const float*)d_in[3];
    const float* bias = (const float*)d_in[4];
    const float* Wout = (const float*)d_in[5];
    const float* bout = (const float*)d_in[6];
    float* out = (float*)d_out;

    cudaFuncSetAttribute(gemm_pipe<true>,  cudaFuncAttributeMaxDynamicSharedMemorySize, GEMM_SMEM);
    cudaFuncSetAttribute(gemm_pipe<false>, cudaFuncAttributeMaxDynamicSharedMemorySize, GEMM_SMEM);
    cudaFuncSetAttribute(lstm_recur,       cudaFuncAttributeMaxDynamicSharedMemorySize, RECUR_SMEM);

    float* zx_p = nullptr;
    uint32_t *hseq_p = nullptr, *emb_tf = nullptr, *w_tf = nullptr, *wout_tf = nullptr;
    unsigned* bar_p = nullptr;
    cudaGetSymbolAddress((void**)&zx_p, g_zx);
    cudaGetSymbolAddress((void**)&hseq_p, g_hseq);
    cudaGetSymbolAddress((void**)&emb_tf, g_emb_tf);
    cudaGetSymbolAddress((void**)&w_tf, g_w_tf);
    cudaGetSymbolAddress((void**)&wout_tf, g_wout_tf);
    cudaGetSymbolAddress((void**)&bar_p, g_bar_count);

    // reset grid-barrier counter (graph-capturable)
    cudaMemsetAsync(bar_p, 0, sizeof(unsigned));

    // pre-convert weights to tf32 (round-to-nearest; exact for later mma loads)
    cvt_tf32<<<1184, 256>>>((const float4*)emb,  (uint4*)emb_tf,  (V_ * E_) / 4);
    cvt_tf32<<<1184, 256>>>((const float4*)W,    (uint4*)w_tf,    (E_ * FH) / 4);
    cvt_tf32<<<1184, 256>>>((const float4*)Wout, (uint4*)wout_tf, (H_ * V_) / 4);

    // K1: zx[T*B, 4H] = emb[x] @ kernel + bias   (M=4096, N=4096, K=512)
    gemm_pipe<true><<<dim3(BT / GTM, FH / GTN), 256, GEMM_SMEM>>>(
        emb_tf, w_tf, bias, zx_p, x, BT, FH, E_);

    // K2: sequential LSTM over T=256 steps (persistent, grid-synced)
    lstm_recur<<<NCTA2, 256, RECUR_SMEM>>>(Wr);

    // K3: logits[BT, V] = hseq @ w_out + b_out   (M=4096, N=32000, K=1024)
    gemm_pipe<false><<<dim3(BT / GTM, V_ / GTN), 256, GEMM_SMEM>>>(
        (const uint32_t*)hseq_p, wout_tf, bout, out, nullptr, BT, V_, H_);
}

// round 5
// speedup vs baseline: 1.4610x; 1.0733x over previous
#include <cuda_runtime.h>
#include <cstdint>

#define V_  32000
#define E_  512
#define H_  1024
#define B_  16
#define T_  256
#define BT  4096
#define FH  4096

// ---------------- scratch (device globals; no allocation allowed) -----------
__device__ float    g_zx[(size_t)BT * FH];       // [T][B][4H] 64MB
__device__ uint32_t g_hseq[(size_t)BT * H_];     // tf32 words 16MB
__device__ uint32_t g_h[B_ * H_];                // current h (tf32 words)
__device__ uint32_t g_emb_tf[(size_t)V_ * E_];   // 65MB
__device__ uint32_t g_wT[(size_t)FH * E_];       // kernel^T [4H,E] tf32 8MB
__device__ uint32_t g_woutT[(size_t)V_ * H_];    // w_out^T [V,H] tf32 131MB
__device__ unsigned g_bar_count;

// ---------------- helpers ----------------------------------------------------
__device__ __forceinline__ uint32_t f2tf(float f) {
    uint32_t u;
    asm("cvt.rna.tf32.f32 %0, %1;" : "=r"(u) : "f"(f));
    return u;
}

__device__ __forceinline__ void mma_tf32(float* c,
                                         uint32_t a0, uint32_t a1, uint32_t a2, uint32_t a3,
                                         uint32_t b0, uint32_t b1) {
    asm volatile(
        "mma.sync.aligned.m16n8k8.row.col.f32.tf32.tf32.f32 "
        "{%0,%1,%2,%3}, {%4,%5,%6,%7}, {%8,%9}, {%0,%1,%2,%3};"
        : "+f"(c[0]), "+f"(c[1]), "+f"(c[2]), "+f"(c[3])
        : "r"(a0), "r"(a1), "r"(a2), "r"(a3), "r"(b0), "r"(b1));
}

__device__ __forceinline__ void ldsm4(uint32_t& r0, uint32_t& r1, uint32_t& r2,
                                      uint32_t& r3, uint32_t addr) {
    asm volatile("ldmatrix.sync.aligned.m8n8.x4.shared.b16 {%0,%1,%2,%3}, [%4];"
                 : "=r"(r0), "=r"(r1), "=r"(r2), "=r"(r3) : "r"(addr));
}

__device__ __forceinline__ float sigf(float x) { return 1.0f / (1.0f + expf(-x)); }

__device__ __forceinline__ void cp16(uint32_t dst, const void* src) {
    asm volatile("cp.async.cg.shared.global [%0], [%1], 16;\n" ::
                 "r"(dst), "l"(src) : "memory");
}
__device__ __forceinline__ void cp_commit() {
    asm volatile("cp.async.commit_group;" ::: "memory");
}
template <int N>
__device__ __forceinline__ void cp_wait() {
    asm volatile("cp.async.wait_group %0;" :: "n"(N) : "memory");
}

// ---------------- fp32 -> tf32 elementwise ------------------------------------
__global__ void cvt_tf32(const float4* __restrict__ src, uint4* __restrict__ dst, int n4) {
    int i = blockIdx.x * blockDim.x + threadIdx.x;
    int stride = gridDim.x * blockDim.x;
    for (; i < n4; i += stride) {
        float4 v = src[i];
        dst[i] = make_uint4(f2tf(v.x), f2tf(v.y), f2tf(v.z), f2tf(v.w));
    }
}

// ---------------- fp32 [K,N] -> tf32 [N,K] transpose ---------------------------
__global__ void __launch_bounds__(256)
transpose_tf(const float* __restrict__ src, uint32_t* __restrict__ dst, int K, int N) {
    __shared__ uint32_t tile[32][33];
    int n0 = blockIdx.x * 32, k0 = blockIdx.y * 32;
    int tx = threadIdx.x & 31, ty = threadIdx.x >> 5;  // 32 x 8
#pragma unroll
    for (int i = 0; i < 4; i++)
        tile[ty + i * 8][tx] = f2tf(src[(size_t)(k0 + ty + i * 8) * N + n0 + tx]);
    __syncthreads();
#pragma unroll
    for (int i = 0; i < 4; i++)
        dst[(size_t)(n0 + ty + i * 8) * K + k0 + tx] = tile[tx][ty + i * 8];
}

// =============================================================================
// Pipelined tf32 GEMM with ldmatrix operand fetch.
//   C[M,N] = gather(A)[M,K] @ Bt[N,K]^T + bias[N]
// A [M,K], Bt [N,K] tf32 words, K-major. CTA tile 128x128, k=32, 3 stages.
// Stage layout (per stage 32KB): A rows 0..127 then B rows 0..127; each row =
// 32 tf32 = 8 chunks of 16B, chunk c of row r placed at (c ^ (r&7))*16.
// 256 threads = 8 warps (2m x 4n of 64x32). 2 CTAs/SM. blockIdx.x = m (fast).
// =============================================================================
#define GTM 128
#define GTN 128
#define GTK 32
#define PS  3
#define A_BYTES (128 * 128)              // 16KB
#define ST_BYTES (2 * A_BYTES)           // 32KB
#define GEMM_SMEM (PS * ST_BYTES)        // 98304 B

template <bool GATHER>
__global__ void __launch_bounds__(256, 2)
gemm_ld(const uint32_t* __restrict__ A, const uint32_t* __restrict__ Bt,
        const float* __restrict__ bias, float* __restrict__ C,
        const int* __restrict__ xs, int M, int N, int K) {
    extern __shared__ uint32_t sm[];
    uint32_t sb;
    asm("{.reg .u64 t; cvta.to.shared.u64 t, %1; cvt.u32.u64 %0, t;}"
        : "=r"(sb) : "l"(sm));

    const int tid  = threadIdx.x;
    const int lane = tid & 31;
    const int wid  = tid >> 5;
    const int m0   = blockIdx.x * GTM;
    const int n0   = blockIdx.y * GTN;
    const int wm   = (wid & 1) * 64;
    const int wn   = (wid >> 1) * 32;
    const int g    = lane >> 2;
    const int tg   = lane & 3;

    float acc[4][4][4];
#pragma unroll
    for (int i = 0; i < 4; i++)
#pragma unroll
        for (int j = 0; j < 4; j++)
#pragma unroll
            for (int k = 0; k < 4; k++) acc[i][j][k] = 0.0f;

    // ---- load geometry: 4 rows x 8 chunks per thread per operand ----
    const int lr = tid >> 3;      // base row 0..31 (stride 32)
    const int lc = tid & 7;       // chunk 0..7
    const uint32_t sw_off = (uint32_t)(lr * 128 + ((lc ^ (lr & 7)) * 16));

    const uint32_t* aptr[4];
#pragma unroll
    for (int i = 0; i < 4; i++) {
        int r = m0 + lr + i * 32;
        int grow = GATHER ? xs[(r & (B_ - 1)) * T_ + (r >> 4)] : r;
        aptr[i] = A + (size_t)grow * K + lc * 4;
    }
    const uint32_t* bptr = Bt + (size_t)(n0 + lr) * K + lc * 4;
    const size_t bstep = (size_t)32 * K;

    const int KT = K / GTK;

    auto load_stage = [&](int st, int kt) {
        const int k0 = kt * GTK;
        const uint32_t ab = sb + st * ST_BYTES + sw_off;
        const uint32_t bb = ab + A_BYTES;
#pragma unroll
        for (int i = 0; i < 4; i++) cp16(ab + i * 32 * 128, aptr[i] + k0);
        const uint32_t* bp = bptr + k0;
#pragma unroll
        for (int i = 0; i < 4; i++) { cp16(bb + i * 32 * 128, bp); bp += bstep; }
    };

    // ---- ldmatrix per-lane addressing ----
    const int l7 = lane & 7;
    const int hb = (lane >> 3) & 1;   // +8 rows (tile1/3)
    const int hc = lane >> 4;         // +1 chunk (tile2/3)
    uint32_t a_row_off[4], b_row_off[2];
#pragma unroll
    for (int mt = 0; mt < 4; mt++)
        a_row_off[mt] = (uint32_t)((wm + mt * 16 + l7 + hb * 8) * 128);
#pragma unroll
    for (int p = 0; p < 2; p++)
        b_row_off[p] = (uint32_t)(A_BYTES + (wn + p * 16 + l7 + hb * 8) * 128);
    uint32_t choff[4];
#pragma unroll
    for (int kk = 0; kk < 4; kk++)
        choff[kk] = (uint32_t)((((2 * kk + hc) ^ l7)) * 16);

    // prologue
#pragma unroll
    for (int p = 0; p < PS - 1; ++p) {
        load_stage(p, p);
        cp_commit();
    }

    for (int kt = 0; kt < KT; ++kt) {
        cp_wait<PS - 2>();
        __syncthreads();
        if (kt + PS - 1 < KT) load_stage((kt + PS - 1) % PS, kt + PS - 1);
        cp_commit();

        const uint32_t st = sb + (uint32_t)(kt % PS) * ST_BYTES;
#pragma unroll
        for (int kk = 0; kk < 4; kk++) {
            const uint32_t co = choff[kk];
            uint32_t bf[4][2];
            ldsm4(bf[0][0], bf[1][0], bf[0][1], bf[1][1], st + b_row_off[0] + co);
            ldsm4(bf[2][0], bf[3][0], bf[2][1], bf[3][1], st + b_row_off[1] + co);
#pragma unroll
            for (int mt = 0; mt < 4; mt++) {
                uint32_t a0, a1, a2, a3;
                ldsm4(a0, a1, a2, a3, st + a_row_off[mt] + co);
#pragma unroll
                for (int nt = 0; nt < 4; nt++)
                    mma_tf32(acc[mt][nt], a0, a1, a2, a3, bf[nt][0], bf[nt][1]);
            }
        }
    }

    // ---- epilogue ----
#pragma unroll
    for (int mt = 0; mt < 4; mt++) {
#pragma unroll
        for (int nt = 0; nt < 4; nt++) {
            int r = m0 + wm + mt * 16 + g;
            int c = n0 + wn + nt * 8 + 2 * tg;
            float2 bb = *reinterpret_cast<const float2*>(bias + c);
            float2 v0 = {acc[mt][nt][0] + bb.x, acc[mt][nt][1] + bb.y};
            float2 v1 = {acc[mt][nt][2] + bb.x, acc[mt][nt][3] + bb.y};
            *reinterpret_cast<float2*>(C + (size_t)r * N + c) = v0;
            *reinterpret_cast<float2*>(C + (size_t)(r + 8) * N + c) = v1;
        }
    }
}

// =============================================================================
// Persistent LSTM recurrence. 128 CTAs, 256 threads. (unchanged)
// =============================================================================
#define NCTA2 128
#define WR_STRIDE 36
#define HS_STRIDE 1028
#define WR_WORDS (H_ * WR_STRIDE)
#define HS_WORDS (B_ * HS_STRIDE)
#define ZS_FLOATS (2 * 16 * 32)
#define RECUR_SMEM ((WR_WORDS + HS_WORDS + ZS_FLOATS) * 4)

__global__ void __launch_bounds__(256, 1)
lstm_recur(const float* __restrict__ rec) {
    extern __shared__ uint32_t sm2[];
    uint32_t* Wr = sm2;
    uint32_t* Hs = sm2 + WR_WORDS;
    float* Zs = reinterpret_cast<float*>(sm2 + WR_WORDS + HS_WORDS);

    const int tid  = threadIdx.x;
    const int lane = tid & 31;
    const int wid  = tid >> 5;
    const int j0   = blockIdx.x * 8;
    const int g    = lane >> 2;
    const int tg   = lane & 3;

    for (int i = tid; i < H_ * 32; i += 256) {
        int k = i >> 5, n = i & 31;
        int gcol = (n >> 3) * H_ + j0 + (n & 7);
        Wr[k * WR_STRIDE + n] = f2tf(rec[(size_t)k * FH + gcol]);
    }

    const int kh  = wid >> 2;
    const int nt  = wid & 3;
    const int nn0 = nt * 8;

    const int gb = tid >> 3;
    const int gj = tid & 7;
    float creg = 0.0f;

    __syncthreads();

    for (int s = 0; s < T_; ++s) {
        float zxi = 0.f, zxf = 0.f, zxg = 0.f, zxo = 0.f;
        if (tid < 128) {
            const float* zx = g_zx + ((size_t)s * B_ + gb) * FH + j0 + gj;
            zxi = zx[0];
            zxf = zx[H_];
            zxg = zx[2 * H_];
            zxo = zx[3 * H_];
        }

        if (s == 0) {
            for (int i = tid; i < HS_WORDS; i += 256) Hs[i] = 0u;
        } else {
#pragma unroll
            for (int i = 0; i < 16; ++i) {
                int idx = tid + i * 256;
                int b = idx >> 8, kq = idx & 255;
                uint4 v = *reinterpret_cast<const uint4*>(g_h + b * H_ + kq * 4);
                *reinterpret_cast<uint4*>(Hs + b * HS_STRIDE + kq * 4) = v;
            }
        }
        __syncthreads();

        float ac[4][4];
#pragma unroll
        for (int i = 0; i < 4; i++)
#pragma unroll
            for (int j = 0; j < 4; j++) ac[i][j] = 0.0f;

        const int kbase = kh * 512;
#pragma unroll 4
        for (int kt = 0; kt < 64; ++kt) {
            int k0 = kbase + kt * 8;
            uint32_t a0 = Hs[g * HS_STRIDE + k0 + tg];
            uint32_t a1 = Hs[(g + 8) * HS_STRIDE + k0 + tg];
            uint32_t a2 = Hs[g * HS_STRIDE + k0 + 4 + tg];
            uint32_t a3 = Hs[(g + 8) * HS_STRIDE + k0 + 4 + tg];
            uint32_t b0 = Wr[(k0 + tg) * WR_STRIDE + nn0 + g];
            uint32_t b1 = Wr[(k0 + 4 + tg) * WR_STRIDE + nn0 + g];
            mma_tf32(ac[kt & 3], a0, a1, a2, a3, b0, b1);
        }
        float c0 = (ac[0][0] + ac[1][0]) + (ac[2][0] + ac[3][0]);
        float c1 = (ac[0][1] + ac[1][1]) + (ac[2][1] + ac[3][1]);
        float c2 = (ac[0][2] + ac[1][2]) + (ac[2][2] + ac[3][2]);
        float c3 = (ac[0][3] + ac[1][3]) + (ac[2][3] + ac[3][3]);

        float* zp = Zs + kh * 512;
        zp[g * 32 + nn0 + 2 * tg]           = c0;
        zp[g * 32 + nn0 + 2 * tg + 1]       = c1;
        zp[(g + 8) * 32 + nn0 + 2 * tg]     = c2;
        zp[(g + 8) * 32 + nn0 + 2 * tg + 1] = c3;
        __syncthreads();

        if (tid < 128) {
            float zi = Zs[gb * 32 + gj]      + Zs[512 + gb * 32 + gj]      + zxi;
            float zf = Zs[gb * 32 + 8 + gj]  + Zs[512 + gb * 32 + 8 + gj]  + zxf;
            float zg = Zs[gb * 32 + 16 + gj] + Zs[512 + gb * 32 + 16 + gj] + zxg;
            float zo = Zs[gb * 32 + 24 + gj] + Zs[512 + gb * 32 + 24 + gj] + zxo;
            creg = sigf(zf) * creg + sigf(zi) * tanhf(zg);
            float hh = sigf(zo) * tanhf(creg);
            uint32_t hw = f2tf(hh);
            g_h[gb * H_ + j0 + gj] = hw;
            g_hseq[((size_t)gb * T_ + s) * H_ + j0 + gj] = hw;
        }
        __syncthreads();

        if (tid == 0) {
            unsigned target = (unsigned)NCTA2 * (unsigned)(s + 1);
            asm volatile("red.release.gpu.global.add.u32 [%0], %1;" ::
                         "l"(&g_bar_count), "r"(1u) : "memory");
            unsigned v;
            do {
                asm volatile("ld.acquire.gpu.global.u32 %0, [%1];"
                             : "=r"(v) : "l"(&g_bar_count) : "memory");
            } while (v < target);
        }
        __syncthreads();
    }
}

// =============================================================================
// host
// =============================================================================
extern "C" void kernel_launch(void* const* d_in, const int* in_sizes, int n_in,
                              void* d_out, int out_size) {
    (void)in_sizes; (void)n_in; (void)out_size;
    const int*   x    = (const int*)d_in[0];
    const float* emb  = (const float*)d_in[1];
    const float* W    = (const float*)d_in[2];
    const float* Wr   = (const float*)d_in[3];
    const float* bias = (const float*)d_in[4];
    const float* Wout = (const float*)d_in[5];
    const float* bout = (const float*)d_in[6];
    float* out = (float*)d_out;

    cudaFuncSetAttribute(gemm_ld<true>,  cudaFuncAttributeMaxDynamicSharedMemorySize, GEMM_SMEM);
    cudaFuncSetAttribute(gemm_ld<false>, cudaFuncAttributeMaxDynamicSharedMemorySize, GEMM_SMEM);
    cudaFuncSetAttribute(lstm_recur,     cudaFuncAttributeMaxDynamicSharedMemorySize, RECUR_SMEM);

    float* zx_p = nullptr;
    uint32_t *hseq_p = nullptr, *emb_tf = nullptr, *wT_p = nullptr, *woutT_p = nullptr;
    unsigned* bar_p = nullptr;
    cudaGetSymbolAddress((void**)&zx_p, g_zx);
    cudaGetSymbolAddress((void**)&hseq_p, g_hseq);
    cudaGetSymbolAddress((void**)&emb_tf, g_emb_tf);
    cudaGetSymbolAddress((void**)&wT_p, g_wT);
    cudaGetSymbolAddress((void**)&woutT_p, g_woutT);
    cudaGetSymbolAddress((void**)&bar_p, g_bar_count);

    cudaMemsetAsync(bar_p, 0, sizeof(unsigned));

    // embedding -> tf32; weights -> transposed tf32 [N,K]
    cvt_tf32<<<1184, 256>>>((const float4*)emb, (uint4*)emb_tf, (V_ * E_) / 4);
    transpose_tf<<<dim3(FH / 32, E_ / 32), 256>>>(W, wT_p, E_, FH);
    transpose_tf<<<dim3(V_ / 32, H_ / 32), 256>>>(Wout, woutT_p, H_, V_);

    // K1: zx[T*B, 4H] = emb[x] @ kernel + bias   (M=4096, N=4096, K=512)
    gemm_ld<true><<<dim3(BT / GTM, FH / GTN), 256, GEMM_SMEM>>>(
        emb_tf, wT_p, bias, zx_p, x, BT, FH, E_);

    // K2: sequential LSTM over T=256 steps (persistent, grid-synced)
    lstm_recur<<<NCTA2, 256, RECUR_SMEM>>>(Wr);

    // K3: logits[BT, V] = hseq @ w_out + b_out   (M=4096, N=32000, K=1024)
    gemm_ld<false><<<dim3(BT / GTM, V_ / GTN), 256, GEMM_SMEM>>>(
        (const uint32_t*)hseq_p, woutT_p, bout, out, nullptr, BT, V_, H_);
}

// round 6
// speedup vs baseline: 2.4055x; 1.6465x over previous
#include <cuda_runtime.h>
#include <cuda_fp16.h>
#include <cstdint>

#define V_  32000
#define E_  512
#define H_  1024
#define B_  16
#define T_  256
#define BT  4096
#define FH  4096

// ---------------- scratch (device globals; no allocation allowed) -----------
__device__ float  g_zx[(size_t)BT * FH];                    // [T][B][4H] 64MB
__device__ __align__(16) __half g_hseq[(size_t)BT * H_];    // fp16 8MB
__device__ __align__(16) __half g_h[B_ * H_];               // current h fp16
__device__ __align__(16) __half g_emb16[(size_t)V_ * E_];   // 33MB
__device__ __align__(16) __half g_wT[(size_t)FH * E_];      // kernel^T [4H,E] 4MB
__device__ __align__(16) __half g_woutT[(size_t)V_ * H_];   // w_out^T [V,H] 65MB
__device__ unsigned g_bar_count;

// ---------------- helpers ----------------------------------------------------
__device__ __forceinline__ uint32_t pack2h(float a, float b) {
    __half2 h = __floats2half2_rn(a, b);
    return *reinterpret_cast<uint32_t*>(&h);
}

__device__ __forceinline__ void mma_f16(float* c,
                                        uint32_t a0, uint32_t a1, uint32_t a2, uint32_t a3,
                                        uint32_t b0, uint32_t b1) {
    asm volatile(
        "mma.sync.aligned.m16n8k16.row.col.f32.f16.f16.f32 "
        "{%0,%1,%2,%3}, {%4,%5,%6,%7}, {%8,%9}, {%0,%1,%2,%3};"
        : "+f"(c[0]), "+f"(c[1]), "+f"(c[2]), "+f"(c[3])
        : "r"(a0), "r"(a1), "r"(a2), "r"(a3), "r"(b0), "r"(b1));
}

__device__ __forceinline__ void ldsm4(uint32_t& r0, uint32_t& r1, uint32_t& r2,
                                      uint32_t& r3, uint32_t addr) {
    asm volatile("ldmatrix.sync.aligned.m8n8.x4.shared.b16 {%0,%1,%2,%3}, [%4];"
                 : "=r"(r0), "=r"(r1), "=r"(r2), "=r"(r3) : "r"(addr));
}

__device__ __forceinline__ float sigf(float x) { return 1.0f / (1.0f + expf(-x)); }

__device__ __forceinline__ void cp16(uint32_t dst, const void* src) {
    asm volatile("cp.async.cg.shared.global [%0], [%1], 16;\n" ::
                 "r"(dst), "l"(src) : "memory");
}
__device__ __forceinline__ void cp_commit() {
    asm volatile("cp.async.commit_group;" ::: "memory");
}
template <int N>
__device__ __forceinline__ void cp_wait() {
    asm volatile("cp.async.wait_group %0;" :: "n"(N) : "memory");
}

// ---------------- fp32 -> fp16 elementwise ------------------------------------
__global__ void cvt_f16(const float4* __restrict__ src, uint2* __restrict__ dst, int n4) {
    int i = blockIdx.x * blockDim.x + threadIdx.x;
    int stride = gridDim.x * blockDim.x;
    for (; i < n4; i += stride) {
        float4 v = src[i];
        uint2 o;
        o.x = pack2h(v.x, v.y);
        o.y = pack2h(v.z, v.w);
        dst[i] = o;
    }
}

// ---------------- fp32 [K,N] -> fp16 [N,K] transpose ---------------------------
__global__ void __launch_bounds__(256)
transpose_f16(const float* __restrict__ src, __half* __restrict__ dst, int K, int N) {
    __shared__ float tile[32][33];
    int n0 = blockIdx.x * 32, k0 = blockIdx.y * 32;
    int tx = threadIdx.x & 31, ty = threadIdx.x >> 5;  // 32 x 8
#pragma unroll
    for (int i = 0; i < 4; i++)
        tile[ty + i * 8][tx] = src[(size_t)(k0 + ty + i * 8) * N + n0 + tx];
    __syncthreads();
#pragma unroll
    for (int i = 0; i < 4; i++)
        dst[(size_t)(n0 + ty + i * 8) * K + k0 + tx] = __float2half_rn(tile[tx][ty + i * 8]);
}

// =============================================================================
// Pipelined fp16 GEMM (f32 accum) with ldmatrix operand fetch.
//   C[M,N] = gather(A)[M,K] @ Bt[N,K]^T + bias[N]
// A [M,K], Bt [N,K] fp16, K-major. CTA tile 128x128, k-tile 64, 3 stages.
// Stage (32KB): A rows 0..127 then B rows 0..127; row = 64 fp16 = 128B = 8
// chunks of 16B; chunk c of row r at (c ^ (r&7))*16.
// 256 threads = 8 warps (2m x 4n of 64x32). 2 CTAs/SM. blockIdx.x = m (fast).
// =============================================================================
#define GTM 128
#define GTN 128
#define GTK 64
#define PS  3
#define A_BYTES (128 * 128)              // 16KB
#define ST_BYTES (2 * A_BYTES)           // 32KB
#define GEMM_SMEM (PS * ST_BYTES)        // 98304 B

template <bool GATHER>
__global__ void __launch_bounds__(256, 2)
gemm_ld(const uint32_t* __restrict__ A, const uint32_t* __restrict__ Bt,
        const float* __restrict__ bias, float* __restrict__ C,
        const int* __restrict__ xs, int M, int N, int K) {
    extern __shared__ uint32_t sm[];
    uint32_t sb;
    asm("{.reg .u64 t; cvta.to.shared.u64 t, %1; cvt.u32.u64 %0, t;}"
        : "=r"(sb) : "l"(sm));

    const int tid  = threadIdx.x;
    const int lane = tid & 31;
    const int wid  = tid >> 5;
    const int m0   = blockIdx.x * GTM;
    const int n0   = blockIdx.y * GTN;
    const int wm   = (wid & 1) * 64;
    const int wn   = (wid >> 1) * 32;
    const int g    = lane >> 2;
    const int tg   = lane & 3;
    const int Kw   = K >> 1;              // 32-bit words per row

    float acc[4][4][4];
#pragma unroll
    for (int i = 0; i < 4; i++)
#pragma unroll
        for (int j = 0; j < 4; j++)
#pragma unroll
            for (int k = 0; k < 4; k++) acc[i][j][k] = 0.0f;

    // ---- load geometry: 4 rows x 8 chunks per thread per operand ----
    const int lr = tid >> 3;      // base row 0..31 (stride 32)
    const int lc = tid & 7;       // chunk 0..7
    const uint32_t sw_off = (uint32_t)(lr * 128 + ((lc ^ (lr & 7)) * 16));

    const uint32_t* aptr[4];
#pragma unroll
    for (int i = 0; i < 4; i++) {
        int r = m0 + lr + i * 32;
        int grow = GATHER ? xs[(r & (B_ - 1)) * T_ + (r >> 4)] : r;
        aptr[i] = A + (size_t)grow * Kw + lc * 4;
    }
    const uint32_t* bptr = Bt + (size_t)(n0 + lr) * Kw + lc * 4;
    const size_t bstep = (size_t)32 * Kw;

    const int KT = K / GTK;

    auto load_stage = [&](int st, int kt) {
        const int k0w = kt * (GTK / 2);
        const uint32_t ab = sb + st * ST_BYTES + sw_off;
        const uint32_t bb = ab + A_BYTES;
#pragma unroll
        for (int i = 0; i < 4; i++) cp16(ab + i * 32 * 128, aptr[i] + k0w);
        const uint32_t* bp = bptr + k0w;
#pragma unroll
        for (int i = 0; i < 4; i++) { cp16(bb + i * 32 * 128, bp); bp += bstep; }
    };

    // ---- ldmatrix per-lane addressing ----
    const int l7 = lane & 7;
    const int hb = (lane >> 3) & 1;   // +8 rows (tiles 1/3)
    const int hc = lane >> 4;         // +1 chunk (tiles 2/3)
    uint32_t a_row_off[4], b_row_off[2];
#pragma unroll
    for (int mt = 0; mt < 4; mt++)
        a_row_off[mt] = (uint32_t)((wm + mt * 16 + l7 + hb * 8) * 128);
#pragma unroll
    for (int p = 0; p < 2; p++)
        b_row_off[p] = (uint32_t)(A_BYTES + (wn + p * 16 + l7 + hb * 8) * 128);
    uint32_t choff[4];
#pragma unroll
    for (int kk = 0; kk < 4; kk++)
        choff[kk] = (uint32_t)((((2 * kk + hc) ^ l7)) * 16);

    // prologue
#pragma unroll
    for (int p = 0; p < PS - 1; ++p) {
        load_stage(p, p);
        cp_commit();
    }

    for (int kt = 0; kt < KT; ++kt) {
        cp_wait<PS - 2>();
        __syncthreads();
        if (kt + PS - 1 < KT) load_stage((kt + PS - 1) % PS, kt + PS - 1);
        cp_commit();

        const uint32_t st = sb + (uint32_t)(kt % PS) * ST_BYTES;
#pragma unroll
        for (int kk = 0; kk < 4; kk++) {   // each kk = 16 K-elements
            const uint32_t co = choff[kk];
            uint32_t bf[4][2];
            ldsm4(bf[0][0], bf[1][0], bf[0][1], bf[1][1], st + b_row_off[0] + co);
            ldsm4(bf[2][0], bf[3][0], bf[2][1], bf[3][1], st + b_row_off[1] + co);
#pragma unroll
            for (int mt = 0; mt < 4; mt++) {
                uint32_t a0, a1, a2, a3;
                ldsm4(a0, a1, a2, a3, st + a_row_off[mt] + co);
#pragma unroll
                for (int nt = 0; nt < 4; nt++)
                    mma_f16(acc[mt][nt], a0, a1, a2, a3, bf[nt][0], bf[nt][1]);
            }
        }
    }

    // ---- epilogue ----
#pragma unroll
    for (int mt = 0; mt < 4; mt++) {
#pragma unroll
        for (int nt = 0; nt < 4; nt++) {
            int r = m0 + wm + mt * 16 + g;
            int c = n0 + wn + nt * 8 + 2 * tg;
            float2 bb = *reinterpret_cast<const float2*>(bias + c);
            float2 v0 = {acc[mt][nt][0] + bb.x, acc[mt][nt][1] + bb.y};
            float2 v1 = {acc[mt][nt][2] + bb.x, acc[mt][nt][3] + bb.y};
            *reinterpret_cast<float2*>(C + (size_t)r * N + c) = v0;
            *reinterpret_cast<float2*>(C + (size_t)(r + 8) * N + c) = v1;
        }
    }
}

// =============================================================================
// Persistent LSTM recurrence, fp16 operands (f32 accum & state).
// 128 CTAs, 256 threads. WrP packed k-pair words [512][32] in shared.
// Hs packed h [16][512 words]. m16n8k16 mma, 32 iters per k-half.
// =============================================================================
#define NCTA2 128
#define WR_STRIDE 36
#define HS_STRIDE 516
#define WR_WORDS (512 * WR_STRIDE)   // 18432
#define HS_WORDS (B_ * HS_STRIDE)    // 8256
#define ZS_FLOATS (2 * 16 * 32)      // 1024
#define RECUR_SMEM ((WR_WORDS + HS_WORDS + ZS_FLOATS) * 4)  // 110848 B

__global__ void __launch_bounds__(256, 1)
lstm_recur(const float* __restrict__ rec) {
    extern __shared__ uint32_t sm2[];
    uint32_t* WrP = sm2;
    uint32_t* Hs = sm2 + WR_WORDS;
    float* Zs = reinterpret_cast<float*>(sm2 + WR_WORDS + HS_WORDS);

    const int tid  = threadIdx.x;
    const int lane = tid & 31;
    const int wid  = tid >> 5;
    const int j0   = blockIdx.x * 8;
    const int g    = lane >> 2;
    const int tg   = lane & 3;

    // load Wr slice once, packed k-pairs: WrP[kp][n], n -> (n/8)*H + j0 + (n&7)
    for (int i = tid; i < 512 * 32; i += 256) {
        int kp = i >> 5, n = i & 31;
        int gcol = (n >> 3) * H_ + j0 + (n & 7);
        float v0 = rec[(size_t)(2 * kp) * FH + gcol];
        float v1 = rec[(size_t)(2 * kp + 1) * FH + gcol];
        WrP[kp * WR_STRIDE + n] = pack2h(v0, v1);
    }

    const int kh  = wid >> 2;
    const int nt  = wid & 3;
    const int nn0 = nt * 8;

    const int gb = tid >> 3;
    const int gj = tid & 7;
    float creg = 0.0f;

    const uint32_t* gh_w = reinterpret_cast<const uint32_t*>(g_h);

    __syncthreads();

    for (int s = 0; s < T_; ++s) {
        // ---- prefetch zx (independent of h) ----
        float zxi = 0.f, zxf = 0.f, zxg = 0.f, zxo = 0.f;
        if (tid < 128) {
            const float* zx = g_zx + ((size_t)s * B_ + gb) * FH + j0 + gj;
            zxi = zx[0];
            zxf = zx[H_];
            zxg = zx[2 * H_];
            zxo = zx[3 * H_];
        }

        // ---- stage h into shared (packed fp16 words) ----
        if (s == 0) {
            for (int i = tid; i < HS_WORDS; i += 256) Hs[i] = 0u;
        } else {
#pragma unroll
            for (int i = 0; i < 8; ++i) {
                int idx = tid + i * 256;   // 0..2047 uint4s
                int b = idx >> 7, q = idx & 127;
                uint4 v = *reinterpret_cast<const uint4*>(gh_w + b * 512 + q * 4);
                *reinterpret_cast<uint4*>(Hs + b * HS_STRIDE + q * 4) = v;
            }
        }
        __syncthreads();

        // ---- z partial = h @ Wr_slice over this warp's k-half ----
        float ac[4][4];
#pragma unroll
        for (int i = 0; i < 4; i++)
#pragma unroll
            for (int j = 0; j < 4; j++) ac[i][j] = 0.0f;

        const int kbase = kh * 256;   // word offset of this k-half
#pragma unroll 4
        for (int kt = 0; kt < 32; ++kt) {
            int kp0 = kbase + kt * 8;   // 8 words = 16 k
            uint32_t a0 = Hs[g * HS_STRIDE + kp0 + tg];
            uint32_t a1 = Hs[(g + 8) * HS_STRIDE + kp0 + tg];
            uint32_t a2 = Hs[g * HS_STRIDE + kp0 + 4 + tg];
            uint32_t a3 = Hs[(g + 8) * HS_STRIDE + kp0 + 4 + tg];
            uint32_t b0 = WrP[(kp0 + tg) * WR_STRIDE + nn0 + g];
            uint32_t b1 = WrP[(kp0 + 4 + tg) * WR_STRIDE + nn0 + g];
            mma_f16(ac[kt & 3], a0, a1, a2, a3, b0, b1);
        }
        float c0 = (ac[0][0] + ac[1][0]) + (ac[2][0] + ac[3][0]);
        float c1 = (ac[0][1] + ac[1][1]) + (ac[2][1] + ac[3][1]);
        float c2 = (ac[0][2] + ac[1][2]) + (ac[2][2] + ac[3][2]);
        float c3 = (ac[0][3] + ac[1][3]) + (ac[2][3] + ac[3][3]);

        float* zp = Zs + kh * 512;
        zp[g * 32 + nn0 + 2 * tg]           = c0;
        zp[g * 32 + nn0 + 2 * tg + 1]       = c1;
        zp[(g + 8) * 32 + nn0 + 2 * tg]     = c2;
        zp[(g + 8) * 32 + nn0 + 2 * tg + 1] = c3;
        __syncthreads();

        // ---- gates + state update (128 threads: (b, jj)) ----
        if (tid < 128) {
            float zi = Zs[gb * 32 + gj]      + Zs[512 + gb * 32 + gj]      + zxi;
            float zf = Zs[gb * 32 + 8 + gj]  + Zs[512 + gb * 32 + 8 + gj]  + zxf;
            float zg = Zs[gb * 32 + 16 + gj] + Zs[512 + gb * 32 + 16 + gj] + zxg;
            float zo = Zs[gb * 32 + 24 + gj] + Zs[512 + gb * 32 + 24 + gj] + zxo;
            creg = sigf(zf) * creg + sigf(zi) * tanhf(zg);
            float hh = sigf(zo) * tanhf(creg);
            __half hv = __float2half_rn(hh);
            g_h[gb * H_ + j0 + gj] = hv;
            g_hseq[((size_t)gb * T_ + s) * H_ + j0 + gj] = hv;
        }
        __syncthreads();

        // ---- grid barrier: monotone counter ----
        if (tid == 0) {
            unsigned target = (unsigned)NCTA2 * (unsigned)(s + 1);
            asm volatile("red.release.gpu.global.add.u32 [%0], %1;" ::
                         "l"(&g_bar_count), "r"(1u) : "memory");
            unsigned v;
            do {
                asm volatile("ld.acquire.gpu.global.u32 %0, [%1];"
                             : "=r"(v) : "l"(&g_bar_count) : "memory");
            } while (v < target);
        }
        __syncthreads();
    }
}

// =============================================================================
// host
// =============================================================================
extern "C" void kernel_launch(void* const* d_in, const int* in_sizes, int n_in,
                              void* d_out, int out_size) {
    (void)in_sizes; (void)n_in; (void)out_size;
    const int*   x    = (const int*)d_in[0];
    const float* emb  = (const float*)d_in[1];
    const float* W    = (const float*)d_in[2];
    const float* Wr   = (const float*)d_in[3];
    const float* bias = (const float*)d_in[4];
    const float* Wout = (const float*)d_in[5];
    const float* bout = (const float*)d_in[6];
    float* out = (float*)d_out;

    cudaFuncSetAttribute(gemm_ld<true>,  cudaFuncAttributeMaxDynamicSharedMemorySize, GEMM_SMEM);
    cudaFuncSetAttribute(gemm_ld<false>, cudaFuncAttributeMaxDynamicSharedMemorySize, GEMM_SMEM);
    cudaFuncSetAttribute(lstm_recur,     cudaFuncAttributeMaxDynamicSharedMemorySize, RECUR_SMEM);

    float* zx_p = nullptr;
    __half *hseq_p = nullptr, *emb16 = nullptr, *wT_p = nullptr, *woutT_p = nullptr;
    unsigned* bar_p = nullptr;
    cudaGetSymbolAddress((void**)&zx_p, g_zx);
    cudaGetSymbolAddress((void**)&hseq_p, g_hseq);
    cudaGetSymbolAddress((void**)&emb16, g_emb16);
    cudaGetSymbolAddress((void**)&wT_p, g_wT);
    cudaGetSymbolAddress((void**)&woutT_p, g_woutT);
    cudaGetSymbolAddress((void**)&bar_p, g_bar_count);

    cudaMemsetAsync(bar_p, 0, sizeof(unsigned));

    // embedding -> fp16; weights -> transposed fp16 [N,K]
    cvt_f16<<<1184, 256>>>((const float4*)emb, (uint2*)emb16, (V_ * E_) / 4);
    transpose_f16<<<dim3(FH / 32, E_ / 32), 256>>>(W, wT_p, E_, FH);
    transpose_f16<<<dim3(V_ / 32, H_ / 32), 256>>>(Wout, woutT_p, H_, V_);

    // K1: zx[T*B, 4H] = emb[x] @ kernel + bias   (M=4096, N=4096, K=512)
    gemm_ld<true><<<dim3(BT / GTM, FH / GTN), 256, GEMM_SMEM>>>(
        (const uint32_t*)emb16, (const uint32_t*)wT_p, bias, zx_p, x, BT, FH, E_);

    // K2: sequential LSTM over T=256 steps (persistent, grid-synced)
    lstm_recur<<<NCTA2, 256, RECUR_SMEM>>>(Wr);

    // K3: logits[BT, V] = hseq @ w_out + b_out   (M=4096, N=32000, K=1024)
    gemm_ld<false><<<dim3(BT / GTM, V_ / GTN), 256, GEMM_SMEM>>>(
        (const uint32_t*)hseq_p, (const uint32_t*)woutT_p, bout, out, nullptr, BT, V_, H_);
}